// round 1
// baseline (speedup 1.0000x reference)
#include <cuda_runtime.h>
#include <math.h>

#define BS 4096
#define NV 778
#define KP 148                       // 135 pose_feat + 10 shape + 3 zero pad
#define VOUT_ELEMS (BS * NV * 3)

// ---------------- scratch (device globals; no allocation) ----------------
__device__ __align__(16) float g_dirs[NV * 3 * KP];   // [v][d][k] combined posedirs|shapedirs|0
__device__ __align__(16) float g_featT[KP * BS];      // [k][b] transposed features
__device__ __align__(16) float g_se3[BS * 192];       // [b][j*12+e] top 3x4 rows of SE3
__device__ float g_off[3 * BS];                       // [d][b] = trans - center
__device__ float g_JS[16 * 3 * 10];                   // J_regressor @ shapedirs
__device__ float g_JT[16 * 3];                        // J_regressor @ v_template

__constant__ int c_parent[16]   = {-1,0,1,2,0,4,5,0,7,8,0,10,11,0,13,14};
__constant__ int c_neworder[21] = {0,13,14,15,16,1,2,3,17,4,5,6,18,10,11,12,19,7,8,9,20};

// ---------------- kernel 0a: build combined dirs with zero pad ----------------
__global__ void k_build_dirs(const float* __restrict__ posedirs,
                             const float* __restrict__ shapedirs) {
    int idx = blockIdx.x * blockDim.x + threadIdx.x;
    const int total = NV * 3 * KP;
    if (idx >= total) return;
    int k  = idx % KP;
    int vd = idx / KP;  // v*3+d
    float val = 0.0f;
    if (k < 135)       val = posedirs[vd * 135 + k];
    else if (k < 145)  val = shapedirs[vd * 10 + (k - 135)];
    g_dirs[idx] = val;
}

// ---------------- kernel 0b: JS / JT ----------------
__global__ void k_jreg(const float* __restrict__ Jreg,
                       const float* __restrict__ shapedirs,
                       const float* __restrict__ v_template) {
    int jd = blockIdx.x;               // 0..47 = j*3+d
    int j = jd / 3, d = jd % 3;
    int tid = threadIdx.x;             // 128 threads
    float acc[11];
#pragma unroll
    for (int i = 0; i < 11; i++) acc[i] = 0.0f;
    for (int v = tid; v < NV; v += 128) {
        float r = Jreg[j * NV + v];
        const float* sd = shapedirs + (v * 3 + d) * 10;
#pragma unroll
        for (int s = 0; s < 10; s++) acc[s] = fmaf(r, sd[s], acc[s]);
        acc[10] = fmaf(r, v_template[v * 3 + d], acc[10]);
    }
    __shared__ float red[128][11];
#pragma unroll
    for (int i = 0; i < 11; i++) red[tid][i] = acc[i];
    __syncthreads();
    for (int off = 64; off > 0; off >>= 1) {
        if (tid < off) {
#pragma unroll
            for (int i = 0; i < 11; i++) red[tid][i] += red[tid + off][i];
        }
        __syncthreads();
    }
    if (tid == 0) {
#pragma unroll
        for (int s = 0; s < 10; s++) g_JS[jd * 10 + s] = red[0][s];
        g_JT[jd] = red[0][10];
    }
}

// ---------------- kernel 1: per-batch pose/rot/SE3 chain ----------------
__global__ void k_batch(const float* __restrict__ root_rotation,
                        const float* __restrict__ pose,
                        const float* __restrict__ shape,
                        const float* __restrict__ trans,
                        const float* __restrict__ hc,
                        const float* __restrict__ hm,
                        float* __restrict__ jout) {  // points at d_out + VOUT_ELEMS
    int b = blockIdx.x * blockDim.x + threadIdx.x;
    if (b >= BS) return;

    float pz[45];
#pragma unroll
    for (int c = 0; c < 45; c++) pz[c] = pose[b * 45 + c];

    float rot[15][9];
    for (int jj = 0; jj < 15; jj++) {
        float ax = hm[3 * jj], ay = hm[3 * jj + 1], az = hm[3 * jj + 2];
        for (int c = 0; c < 45; c++) {
            float p = pz[c];
            const float* h = hc + c * 45 + 3 * jj;
            ax = fmaf(p, h[0], ax);
            ay = fmaf(p, h[1], ay);
            az = fmaf(p, h[2], az);
        }
        float a2  = ax * ax + ay * ay + az * az + 1e-12f;
        float ang = sqrtf(a2);
        float inv = 1.0f / ang;
        float ux = ax * inv, uy = ay * inv, uz = az * inv;
        float cc = cosf(ang), ss = sinf(ang), oc = 1.0f - cc;
        float R00 = cc + oc * ux * ux;
        float R01 = -ss * uz + oc * ux * uy;
        float R02 =  ss * uy + oc * ux * uz;
        float R10 =  ss * uz + oc * ux * uy;
        float R11 = cc + oc * uy * uy;
        float R12 = -ss * ux + oc * uy * uz;
        float R20 = -ss * uy + oc * ux * uz;
        float R21 =  ss * ux + oc * uy * uz;
        float R22 = cc + oc * uz * uz;
        rot[jj][0]=R00; rot[jj][1]=R01; rot[jj][2]=R02;
        rot[jj][3]=R10; rot[jj][4]=R11; rot[jj][5]=R12;
        rot[jj][6]=R20; rot[jj][7]=R21; rot[jj][8]=R22;
        // pose_feat = (R - I), stored transposed [k][b]
        g_featT[(9*jj+0)*BS + b] = R00 - 1.0f;
        g_featT[(9*jj+1)*BS + b] = R01;
        g_featT[(9*jj+2)*BS + b] = R02;
        g_featT[(9*jj+3)*BS + b] = R10;
        g_featT[(9*jj+4)*BS + b] = R11 - 1.0f;
        g_featT[(9*jj+5)*BS + b] = R12;
        g_featT[(9*jj+6)*BS + b] = R20;
        g_featT[(9*jj+7)*BS + b] = R21;
        g_featT[(9*jj+8)*BS + b] = R22 - 1.0f;
    }

    float sh[10];
#pragma unroll
    for (int s = 0; s < 10; s++) {
        sh[s] = shape[b * 10 + s];
        g_featT[(135 + s) * BS + b] = sh[s];
    }
#pragma unroll
    for (int z = 0; z < 3; z++) g_featT[(145 + z) * BS + b] = 0.0f;

    // j_tpose
    float jt[16][3];
    for (int j = 0; j < 16; j++) {
#pragma unroll
        for (int d = 0; d < 3; d++) {
            float a = g_JT[j * 3 + d];
            const float* js = g_JS + (j * 3 + d) * 10;
#pragma unroll
            for (int s = 0; s < 10; s++) a = fmaf(js[s], sh[s], a);
            jt[j][d] = a;
        }
    }

    // SE3 chain (rows 3x4)
    float A[16][12];
    {
        float Rr[9];
#pragma unroll
        for (int i = 0; i < 9; i++) Rr[i] = root_rotation[b * 9 + i];
        float jx = jt[0][0], jy = jt[0][1], jz = jt[0][2];
#pragma unroll
        for (int r = 0; r < 3; r++) {
            A[0][r*4+0] = Rr[r*3+0];
            A[0][r*4+1] = Rr[r*3+1];
            A[0][r*4+2] = Rr[r*3+2];
        }
        A[0][3]  = jx - (Rr[0]*jx + Rr[1]*jy + Rr[2]*jz);
        A[0][7]  = jy - (Rr[3]*jx + Rr[4]*jy + Rr[5]*jz);
        A[0][11] = jz - (Rr[6]*jx + Rr[7]*jy + Rr[8]*jz);
    }
    for (int i = 1; i < 16; i++) {
        int p = c_parent[i];
        const float* Ri = rot[i - 1];
        float jx = jt[i][0], jy = jt[i][1], jz = jt[i][2];
        float t0 = jx - (Ri[0]*jx + Ri[1]*jy + Ri[2]*jz);
        float t1 = jy - (Ri[3]*jx + Ri[4]*jy + Ri[5]*jz);
        float t2 = jz - (Ri[6]*jx + Ri[7]*jy + Ri[8]*jz);
        const float* P = A[p];
        float* O = A[i];
#pragma unroll
        for (int r = 0; r < 3; r++) {
            float p0 = P[r*4+0], p1 = P[r*4+1], p2 = P[r*4+2];
            O[r*4+0] = p0*Ri[0] + p1*Ri[3] + p2*Ri[6];
            O[r*4+1] = p0*Ri[1] + p1*Ri[4] + p2*Ri[7];
            O[r*4+2] = p0*Ri[2] + p1*Ri[5] + p2*Ri[8];
            O[r*4+3] = p0*t0 + p1*t1 + p2*t2 + P[r*4+3];
        }
    }
    // store SE3
    for (int j = 0; j < 16; j++)
#pragma unroll
        for (int e = 0; e < 12; e++) g_se3[b * 192 + j * 12 + e] = A[j][e];

    // center / offset
    float cx = jt[0][0], cy = jt[0][1], cz = jt[0][2];
    float ox = trans[b*3+0] - cx, oy = trans[b*3+1] - cy, oz = trans[b*3+2] - cz;
    g_off[0*BS + b] = ox;
    g_off[1*BS + b] = oy;
    g_off[2*BS + b] = oz;

    // joint outputs (non-tip entries of j_out)
    float jl[16][3];
    jl[0][0] = cx; jl[0][1] = cy; jl[0][2] = cz;
    for (int i = 1; i < 16; i++) {
        int p = c_parent[i];
        const float* P = A[p];
        float jx = jt[i][0], jy = jt[i][1], jz = jt[i][2];
        jl[i][0] = P[0]*jx + P[1]*jy + P[2]*jz  + P[3];
        jl[i][1] = P[4]*jx + P[5]*jy + P[6]*jz  + P[7];
        jl[i][2] = P[8]*jx + P[9]*jy + P[10]*jz + P[11];
    }
    for (int pos = 0; pos < 21; pos++) {
        int src = c_neworder[pos];
        if (src < 16) {
            float* jo = jout + ((size_t)b * 21 + pos) * 3;
            jo[0] = jl[src][0] + ox;
            jo[1] = jl[src][1] + oy;
            jo[2] = jl[src][2] + oz;
        }
    }
}

// ---------------- kernel 2: main fused GEMM + LBS ----------------
union F4 { float4 v; float a[4]; };

__global__ void __launch_bounds__(256) k_main(const float* __restrict__ v_template,
                                              const float* __restrict__ weights,
                                              float* __restrict__ out) {
    int warp = threadIdx.x >> 5;
    int lane = threadIdx.x & 31;
    int v = blockIdx.x * 8 + warp;
    if (v >= NV) return;
    int b0 = blockIdx.y * 128 + lane * 4;

    const float* dir0 = g_dirs + (v * 3 + 0) * KP;
    const float* dir1 = g_dirs + (v * 3 + 1) * KP;
    const float* dir2 = g_dirs + (v * 3 + 2) * KP;

    float acc0[4] = {0,0,0,0};
    float acc1[4] = {0,0,0,0};
    float acc2[4] = {0,0,0,0};

    for (int k0 = 0; k0 < KP; k0 += 4) {
        F4 p0, p1, p2;
        p0.v = *reinterpret_cast<const float4*>(dir0 + k0);
        p1.v = *reinterpret_cast<const float4*>(dir1 + k0);
        p2.v = *reinterpret_cast<const float4*>(dir2 + k0);
#pragma unroll
        for (int kk = 0; kk < 4; kk++) {
            F4 f;
            f.v = *reinterpret_cast<const float4*>(g_featT + (k0 + kk) * BS + b0);
#pragma unroll
            for (int i = 0; i < 4; i++) {
                acc0[i] = fmaf(p0.a[kk], f.a[i], acc0[i]);
                acc1[i] = fmaf(p1.a[kk], f.a[i], acc1[i]);
                acc2[i] = fmaf(p2.a[kk], f.a[i], acc2[i]);
            }
        }
    }

    float vt0 = v_template[v * 3 + 0];
    float vt1 = v_template[v * 3 + 1];
    float vt2 = v_template[v * 3 + 2];

    float w[16];
#pragma unroll
    for (int j = 0; j < 16; j++) w[j] = weights[v * 16 + j];

#pragma unroll
    for (int i = 0; i < 4; i++) {
        int b = b0 + i;
        float hx = acc0[i] + vt0;
        float hy = acc1[i] + vt1;
        float hz = acc2[i] + vt2;
        const float4* se = reinterpret_cast<const float4*>(g_se3 + (size_t)b * 192);
        float r0 = 0.0f, r1 = 0.0f, r2 = 0.0f;
#pragma unroll
        for (int j = 0; j < 16; j++) {
            float wj = w[j];
            float4 m0 = se[j * 3 + 0];
            float4 m1 = se[j * 3 + 1];
            float4 m2 = se[j * 3 + 2];
            r0 = fmaf(wj, fmaf(m0.x, hx, fmaf(m0.y, hy, fmaf(m0.z, hz, m0.w))), r0);
            r1 = fmaf(wj, fmaf(m1.x, hx, fmaf(m1.y, hy, fmaf(m1.z, hz, m1.w))), r1);
            r2 = fmaf(wj, fmaf(m2.x, hx, fmaf(m2.y, hy, fmaf(m2.z, hz, m2.w))), r2);
        }
        float o0 = r0 + g_off[0 * BS + b];
        float o1 = r1 + g_off[1 * BS + b];
        float o2 = r2 + g_off[2 * BS + b];
        float* vo = out + ((size_t)b * NV + v) * 3;
        vo[0] = o0; vo[1] = o1; vo[2] = o2;

        int pos = -1;
        if      (v == 745) pos = 4;
        else if (v == 333) pos = 8;
        else if (v == 444) pos = 12;
        else if (v == 555) pos = 16;
        else if (v == 672) pos = 20;
        if (pos >= 0) {
            float* jo = out + (size_t)VOUT_ELEMS + ((size_t)b * 21 + pos) * 3;
            jo[0] = o0; jo[1] = o1; jo[2] = o2;
        }
    }
}

// ---------------- launch ----------------
extern "C" void kernel_launch(void* const* d_in, const int* in_sizes, int n_in,
                              void* d_out, int out_size) {
    const float* root_rotation = (const float*)d_in[0];
    const float* pose          = (const float*)d_in[1];
    const float* shape         = (const float*)d_in[2];
    const float* trans         = (const float*)d_in[3];
    const float* hc            = (const float*)d_in[4];
    const float* hm            = (const float*)d_in[5];
    const float* shapedirs     = (const float*)d_in[6];
    const float* posedirs      = (const float*)d_in[7];
    const float* v_template    = (const float*)d_in[8];
    const float* Jreg          = (const float*)d_in[9];
    const float* weights       = (const float*)d_in[10];
    float* out = (float*)d_out;

    int dirs_total = NV * 3 * KP;
    k_build_dirs<<<(dirs_total + 255) / 256, 256>>>(posedirs, shapedirs);
    k_jreg<<<48, 128>>>(Jreg, shapedirs, v_template);
    k_batch<<<BS / 128, 128>>>(root_rotation, pose, shape, trans, hc, hm,
                               out + VOUT_ELEMS);
    dim3 grid((NV + 7) / 8, BS / 128);
    k_main<<<grid, 256>>>(v_template, weights, out);
}

// round 2
// speedup vs baseline: 2.7546x; 2.7546x over previous
#include <cuda_runtime.h>
#include <math.h>

#define BS 4096
#define NV 778
#define KP 148                       // 135 pose_feat + 10 shape + 3 zero pad
#define VOUT_ELEMS (BS * NV * 3)
#define RS 388                       // smem out row stride (floats), 384 data + pad

// ---------------- scratch (device globals; no allocation) ----------------
__device__ __align__(16) float g_dirs[NV * 3 * KP];   // [v][d][k] combined posedirs|shapedirs|0
__device__ __align__(16) float g_featT[KP * BS];      // [k][b] transposed features
__device__ __align__(16) float g_se3T[192 * BS];      // [e][b] transposed SE3 elements (e=j*12+r*4+c)
__device__ __align__(16) float g_off[3 * BS];         // [d][b] = trans - center
__device__ float g_JS[16 * 3 * 10];                   // J_regressor @ shapedirs
__device__ float g_JT[16 * 3];                        // J_regressor @ v_template

__constant__ int c_parent[16]   = {-1,0,1,2,0,4,5,0,7,8,0,10,11,0,13,14};
__constant__ int c_neworder[21] = {0,13,14,15,16,1,2,3,17,4,5,6,18,10,11,12,19,7,8,9,20};

// ---------------- kernel 0a: build combined dirs with zero pad ----------------
__global__ void k_build_dirs(const float* __restrict__ posedirs,
                             const float* __restrict__ shapedirs) {
    int idx = blockIdx.x * blockDim.x + threadIdx.x;
    const int total = NV * 3 * KP;
    if (idx >= total) return;
    int k  = idx % KP;
    int vd = idx / KP;  // v*3+d
    float val = 0.0f;
    if (k < 135)       val = posedirs[vd * 135 + k];
    else if (k < 145)  val = shapedirs[vd * 10 + (k - 135)];
    g_dirs[idx] = val;
}

// ---------------- kernel 0b: JS / JT ----------------
__global__ void k_jreg(const float* __restrict__ Jreg,
                       const float* __restrict__ shapedirs,
                       const float* __restrict__ v_template) {
    int jd = blockIdx.x;               // 0..47 = j*3+d
    int j = jd / 3, d = jd % 3;
    int tid = threadIdx.x;             // 128 threads
    float acc[11];
#pragma unroll
    for (int i = 0; i < 11; i++) acc[i] = 0.0f;
    for (int v = tid; v < NV; v += 128) {
        float r = Jreg[j * NV + v];
        const float* sd = shapedirs + (v * 3 + d) * 10;
#pragma unroll
        for (int s = 0; s < 10; s++) acc[s] = fmaf(r, sd[s], acc[s]);
        acc[10] = fmaf(r, v_template[v * 3 + d], acc[10]);
    }
    __shared__ float red[128][11];
#pragma unroll
    for (int i = 0; i < 11; i++) red[tid][i] = acc[i];
    __syncthreads();
    for (int off = 64; off > 0; off >>= 1) {
        if (tid < off) {
#pragma unroll
            for (int i = 0; i < 11; i++) red[tid][i] += red[tid + off][i];
        }
        __syncthreads();
    }
    if (tid == 0) {
#pragma unroll
        for (int s = 0; s < 10; s++) g_JS[jd * 10 + s] = red[0][s];
        g_JT[jd] = red[0][10];
    }
}

// ---------------- kernel 1: per-batch pose/rot/SE3 chain ----------------
__global__ void k_batch(const float* __restrict__ root_rotation,
                        const float* __restrict__ pose,
                        const float* __restrict__ shape,
                        const float* __restrict__ trans,
                        const float* __restrict__ hc,
                        const float* __restrict__ hm,
                        float* __restrict__ jout) {  // points at d_out + VOUT_ELEMS
    int b = blockIdx.x * blockDim.x + threadIdx.x;
    if (b >= BS) return;

    float pz[45];
#pragma unroll
    for (int c = 0; c < 45; c++) pz[c] = pose[b * 45 + c];

    float rot[15][9];
    for (int jj = 0; jj < 15; jj++) {
        float ax = hm[3 * jj], ay = hm[3 * jj + 1], az = hm[3 * jj + 2];
        for (int c = 0; c < 45; c++) {
            float p = pz[c];
            const float* h = hc + c * 45 + 3 * jj;
            ax = fmaf(p, h[0], ax);
            ay = fmaf(p, h[1], ay);
            az = fmaf(p, h[2], az);
        }
        float a2  = ax * ax + ay * ay + az * az + 1e-12f;
        float ang = sqrtf(a2);
        float inv = 1.0f / ang;
        float ux = ax * inv, uy = ay * inv, uz = az * inv;
        float cc = cosf(ang), ss = sinf(ang), oc = 1.0f - cc;
        float R00 = cc + oc * ux * ux;
        float R01 = -ss * uz + oc * ux * uy;
        float R02 =  ss * uy + oc * ux * uz;
        float R10 =  ss * uz + oc * ux * uy;
        float R11 = cc + oc * uy * uy;
        float R12 = -ss * ux + oc * uy * uz;
        float R20 = -ss * uy + oc * ux * uz;
        float R21 =  ss * ux + oc * uy * uz;
        float R22 = cc + oc * uz * uz;
        rot[jj][0]=R00; rot[jj][1]=R01; rot[jj][2]=R02;
        rot[jj][3]=R10; rot[jj][4]=R11; rot[jj][5]=R12;
        rot[jj][6]=R20; rot[jj][7]=R21; rot[jj][8]=R22;
        // pose_feat = (R - I), stored transposed [k][b]
        g_featT[(9*jj+0)*BS + b] = R00 - 1.0f;
        g_featT[(9*jj+1)*BS + b] = R01;
        g_featT[(9*jj+2)*BS + b] = R02;
        g_featT[(9*jj+3)*BS + b] = R10;
        g_featT[(9*jj+4)*BS + b] = R11 - 1.0f;
        g_featT[(9*jj+5)*BS + b] = R12;
        g_featT[(9*jj+6)*BS + b] = R20;
        g_featT[(9*jj+7)*BS + b] = R21;
        g_featT[(9*jj+8)*BS + b] = R22 - 1.0f;
    }

    float sh[10];
#pragma unroll
    for (int s = 0; s < 10; s++) {
        sh[s] = shape[b * 10 + s];
        g_featT[(135 + s) * BS + b] = sh[s];
    }
#pragma unroll
    for (int z = 0; z < 3; z++) g_featT[(145 + z) * BS + b] = 0.0f;

    // j_tpose
    float jt[16][3];
    for (int j = 0; j < 16; j++) {
#pragma unroll
        for (int d = 0; d < 3; d++) {
            float a = g_JT[j * 3 + d];
            const float* js = g_JS + (j * 3 + d) * 10;
#pragma unroll
            for (int s = 0; s < 10; s++) a = fmaf(js[s], sh[s], a);
            jt[j][d] = a;
        }
    }

    // SE3 chain (rows 3x4)
    float A[16][12];
    {
        float Rr[9];
#pragma unroll
        for (int i = 0; i < 9; i++) Rr[i] = root_rotation[b * 9 + i];
        float jx = jt[0][0], jy = jt[0][1], jz = jt[0][2];
#pragma unroll
        for (int r = 0; r < 3; r++) {
            A[0][r*4+0] = Rr[r*3+0];
            A[0][r*4+1] = Rr[r*3+1];
            A[0][r*4+2] = Rr[r*3+2];
        }
        A[0][3]  = jx - (Rr[0]*jx + Rr[1]*jy + Rr[2]*jz);
        A[0][7]  = jy - (Rr[3]*jx + Rr[4]*jy + Rr[5]*jz);
        A[0][11] = jz - (Rr[6]*jx + Rr[7]*jy + Rr[8]*jz);
    }
    for (int i = 1; i < 16; i++) {
        int p = c_parent[i];
        const float* Ri = rot[i - 1];
        float jx = jt[i][0], jy = jt[i][1], jz = jt[i][2];
        float t0 = jx - (Ri[0]*jx + Ri[1]*jy + Ri[2]*jz);
        float t1 = jy - (Ri[3]*jx + Ri[4]*jy + Ri[5]*jz);
        float t2 = jz - (Ri[6]*jx + Ri[7]*jy + Ri[8]*jz);
        const float* P = A[p];
        float* O = A[i];
#pragma unroll
        for (int r = 0; r < 3; r++) {
            float p0 = P[r*4+0], p1 = P[r*4+1], p2 = P[r*4+2];
            O[r*4+0] = p0*Ri[0] + p1*Ri[3] + p2*Ri[6];
            O[r*4+1] = p0*Ri[1] + p1*Ri[4] + p2*Ri[7];
            O[r*4+2] = p0*Ri[2] + p1*Ri[5] + p2*Ri[8];
            O[r*4+3] = p0*t0 + p1*t1 + p2*t2 + P[r*4+3];
        }
    }
    // store SE3 TRANSPOSED: [e][b] so k_main reads are coalesced
    for (int j = 0; j < 16; j++)
#pragma unroll
        for (int e = 0; e < 12; e++) g_se3T[(j * 12 + e) * BS + b] = A[j][e];

    // center / offset
    float cx = jt[0][0], cy = jt[0][1], cz = jt[0][2];
    float ox = trans[b*3+0] - cx, oy = trans[b*3+1] - cy, oz = trans[b*3+2] - cz;
    g_off[0*BS + b] = ox;
    g_off[1*BS + b] = oy;
    g_off[2*BS + b] = oz;

    // joint outputs (non-tip entries of j_out)
    float jl[16][3];
    jl[0][0] = cx; jl[0][1] = cy; jl[0][2] = cz;
    for (int i = 1; i < 16; i++) {
        int p = c_parent[i];
        const float* P = A[p];
        float jx = jt[i][0], jy = jt[i][1], jz = jt[i][2];
        jl[i][0] = P[0]*jx + P[1]*jy + P[2]*jz  + P[3];
        jl[i][1] = P[4]*jx + P[5]*jy + P[6]*jz  + P[7];
        jl[i][2] = P[8]*jx + P[9]*jy + P[10]*jz + P[11];
    }
    for (int pos = 0; pos < 21; pos++) {
        int src = c_neworder[pos];
        if (src < 16) {
            float* jo = jout + ((size_t)b * 21 + pos) * 3;
            jo[0] = jl[src][0] + ox;
            jo[1] = jl[src][1] + oy;
            jo[2] = jl[src][2] + oz;
        }
    }
}

// ---------------- kernel 2: main fused GEMM + LBS ----------------
union F4 { float4 v; float a[4]; };

__global__ void __launch_bounds__(256) k_main(const float* __restrict__ v_template,
                                              const float* __restrict__ weights,
                                              float* __restrict__ out) {
    __shared__ float s_out[8 * RS];   // [v_local][b_local*3+d] (padded rows)

    int warp = threadIdx.x >> 5;
    int lane = threadIdx.x & 31;
    int v = blockIdx.x * 8 + warp;
    int b0 = blockIdx.y * 128 + lane * 4;
    bool valid = (v < NV);

    if (valid) {
        const float* dir0 = g_dirs + (v * 3 + 0) * KP;
        const float* dir1 = g_dirs + (v * 3 + 1) * KP;
        const float* dir2 = g_dirs + (v * 3 + 2) * KP;

        float acc0[4] = {0,0,0,0};
        float acc1[4] = {0,0,0,0};
        float acc2[4] = {0,0,0,0};

        for (int k0 = 0; k0 < KP; k0 += 4) {
            F4 p0, p1, p2;
            p0.v = *reinterpret_cast<const float4*>(dir0 + k0);
            p1.v = *reinterpret_cast<const float4*>(dir1 + k0);
            p2.v = *reinterpret_cast<const float4*>(dir2 + k0);
#pragma unroll
            for (int kk = 0; kk < 4; kk++) {
                F4 f;
                f.v = *reinterpret_cast<const float4*>(g_featT + (k0 + kk) * BS + b0);
#pragma unroll
                for (int i = 0; i < 4; i++) {
                    acc0[i] = fmaf(p0.a[kk], f.a[i], acc0[i]);
                    acc1[i] = fmaf(p1.a[kk], f.a[i], acc1[i]);
                    acc2[i] = fmaf(p2.a[kk], f.a[i], acc2[i]);
                }
            }
        }

        float vt0 = v_template[v * 3 + 0];
        float vt1 = v_template[v * 3 + 1];
        float vt2 = v_template[v * 3 + 2];

        float hx[4], hy[4], hz[4];
#pragma unroll
        for (int i = 0; i < 4; i++) {
            hx[i] = acc0[i] + vt0;
            hy[i] = acc1[i] + vt1;
            hz[i] = acc2[i] + vt2;
        }

        float r0[4] = {0,0,0,0};
        float r1[4] = {0,0,0,0};
        float r2[4] = {0,0,0,0};

#pragma unroll
        for (int j = 0; j < 16; j++) {
            float wj = weights[v * 16 + j];
            const float* base = g_se3T + (size_t)(j * 12) * BS + b0;
            // row 0 (elements 0..3)
            {
                F4 m0, m1, m2, m3;
                m0.v = *reinterpret_cast<const float4*>(base + 0 * BS);
                m1.v = *reinterpret_cast<const float4*>(base + 1 * BS);
                m2.v = *reinterpret_cast<const float4*>(base + 2 * BS);
                m3.v = *reinterpret_cast<const float4*>(base + 3 * BS);
#pragma unroll
                for (int i = 0; i < 4; i++) {
                    float t = fmaf(m0.a[i], hx[i], fmaf(m1.a[i], hy[i], fmaf(m2.a[i], hz[i], m3.a[i])));
                    r0[i] = fmaf(wj, t, r0[i]);
                }
            }
            // row 1 (elements 4..7)
            {
                F4 m0, m1, m2, m3;
                m0.v = *reinterpret_cast<const float4*>(base + 4 * BS);
                m1.v = *reinterpret_cast<const float4*>(base + 5 * BS);
                m2.v = *reinterpret_cast<const float4*>(base + 6 * BS);
                m3.v = *reinterpret_cast<const float4*>(base + 7 * BS);
#pragma unroll
                for (int i = 0; i < 4; i++) {
                    float t = fmaf(m0.a[i], hx[i], fmaf(m1.a[i], hy[i], fmaf(m2.a[i], hz[i], m3.a[i])));
                    r1[i] = fmaf(wj, t, r1[i]);
                }
            }
            // row 2 (elements 8..11)
            {
                F4 m0, m1, m2, m3;
                m0.v = *reinterpret_cast<const float4*>(base + 8 * BS);
                m1.v = *reinterpret_cast<const float4*>(base + 9 * BS);
                m2.v = *reinterpret_cast<const float4*>(base + 10 * BS);
                m3.v = *reinterpret_cast<const float4*>(base + 11 * BS);
#pragma unroll
                for (int i = 0; i < 4; i++) {
                    float t = fmaf(m0.a[i], hx[i], fmaf(m1.a[i], hy[i], fmaf(m2.a[i], hz[i], m3.a[i])));
                    r2[i] = fmaf(wj, t, r2[i]);
                }
            }
        }

        F4 off0, off1, off2;
        off0.v = *reinterpret_cast<const float4*>(g_off + 0 * BS + b0);
        off1.v = *reinterpret_cast<const float4*>(g_off + 1 * BS + b0);
        off2.v = *reinterpret_cast<const float4*>(g_off + 2 * BS + b0);

#pragma unroll
        for (int i = 0; i < 4; i++) {
            float o0 = r0[i] + off0.a[i];
            float o1 = r1[i] + off1.a[i];
            float o2 = r2[i] + off2.a[i];
            int bl = lane * 4 + i;   // local batch index 0..127
            s_out[warp * RS + bl * 3 + 0] = o0;
            s_out[warp * RS + bl * 3 + 1] = o1;
            s_out[warp * RS + bl * 3 + 2] = o2;

            int pos = -1;
            if      (v == 745) pos = 4;
            else if (v == 333) pos = 8;
            else if (v == 444) pos = 12;
            else if (v == 555) pos = 16;
            else if (v == 672) pos = 20;
            if (pos >= 0) {
                int b = b0 + i;
                float* jo = out + (size_t)VOUT_ELEMS + ((size_t)b * 21 + pos) * 3;
                jo[0] = o0; jo[1] = o1; jo[2] = o2;
            }
        }
    }

    __syncthreads();

    // cooperative coalesced readout: per batch, the block's 8 vertices are
    // 24 contiguous floats in out[(b*NV + v_base)*3 ...]
    int v_base = blockIdx.x * 8;
    int b_base = blockIdx.y * 128;
    int nv_here = NV - v_base;
    if (nv_here > 8) nv_here = 8;
    int row_floats = nv_here * 3;
#pragma unroll 4
    for (int t = threadIdx.x; t < 128 * 24; t += 256) {
        int b_local = t / 24;
        int e = t % 24;
        if (e < row_floats) {
            int v_local = e / 3;
            int d = e - v_local * 3;
            out[((size_t)(b_base + b_local) * NV + v_base) * 3 + e] =
                s_out[v_local * RS + b_local * 3 + d];
        }
    }
}

// ---------------- launch ----------------
extern "C" void kernel_launch(void* const* d_in, const int* in_sizes, int n_in,
                              void* d_out, int out_size) {
    const float* root_rotation = (const float*)d_in[0];
    const float* pose          = (const float*)d_in[1];
    const float* shape         = (const float*)d_in[2];
    const float* trans         = (const float*)d_in[3];
    const float* hc            = (const float*)d_in[4];
    const float* hm            = (const float*)d_in[5];
    const float* shapedirs     = (const float*)d_in[6];
    const float* posedirs      = (const float*)d_in[7];
    const float* v_template    = (const float*)d_in[8];
    const float* Jreg          = (const float*)d_in[9];
    const float* weights       = (const float*)d_in[10];
    float* out = (float*)d_out;

    int dirs_total = NV * 3 * KP;
    k_build_dirs<<<(dirs_total + 255) / 256, 256>>>(posedirs, shapedirs);
    k_jreg<<<48, 128>>>(Jreg, shapedirs, v_template);
    k_batch<<<BS / 128, 128>>>(root_rotation, pose, shape, trans, hc, hm,
                               out + VOUT_ELEMS);
    dim3 grid((NV + 7) / 8, BS / 128);
    k_main<<<grid, 256>>>(v_template, weights, out);
}

// round 3
// speedup vs baseline: 3.3455x; 1.2145x over previous
#include <cuda_runtime.h>
#include <math.h>

#define BS 4096
#define NV 778
#define KP 148                       // 135 pose_feat + 10 shape + 3 zero pad
#define VOUT_ELEMS (BS * NV * 3)
#define RS 388                       // smem out row stride (floats), 384 data + pad

// ---------------- scratch (device globals; no allocation) ----------------
__device__ __align__(16) float g_dirs[NV * 3 * KP];   // [v][d][k] combined posedirs|shapedirs|0
__device__ __align__(16) float g_featT[KP * BS];      // [k][b] transposed features
__device__ __align__(16) float g_se3T[192 * BS];      // [e][b] transposed SE3 elements (e=j*12+r*4+c)
__device__ __align__(16) float g_off[3 * BS];         // [d][b] = trans - center
__device__ float g_JS[16 * 3 * 10];                   // J_regressor @ shapedirs
__device__ float g_JT[16 * 3];                        // J_regressor @ v_template

__constant__ int c_parent[16]   = {-1,0,1,2,0,4,5,0,7,8,0,10,11,0,13,14};
__constant__ int c_neworder[21] = {0,13,14,15,16,1,2,3,17,4,5,6,18,10,11,12,19,7,8,9,20};

// ---------------- kernel 0a: build combined dirs with zero pad ----------------
__global__ void k_build_dirs(const float* __restrict__ posedirs,
                             const float* __restrict__ shapedirs) {
    int idx = blockIdx.x * blockDim.x + threadIdx.x;
    const int total = NV * 3 * KP;
    if (idx >= total) return;
    int k  = idx % KP;
    int vd = idx / KP;  // v*3+d
    float val = 0.0f;
    if (k < 135)       val = posedirs[vd * 135 + k];
    else if (k < 145)  val = shapedirs[vd * 10 + (k - 135)];
    g_dirs[idx] = val;
}

// ---------------- kernel 0b: JS / JT ----------------
__global__ void k_jreg(const float* __restrict__ Jreg,
                       const float* __restrict__ shapedirs,
                       const float* __restrict__ v_template) {
    int jd = blockIdx.x;               // 0..47 = j*3+d
    int j = jd / 3, d = jd % 3;
    int tid = threadIdx.x;             // 128 threads
    float acc[11];
#pragma unroll
    for (int i = 0; i < 11; i++) acc[i] = 0.0f;
    for (int v = tid; v < NV; v += 128) {
        float r = Jreg[j * NV + v];
        const float* sd = shapedirs + (v * 3 + d) * 10;
#pragma unroll
        for (int s = 0; s < 10; s++) acc[s] = fmaf(r, sd[s], acc[s]);
        acc[10] = fmaf(r, v_template[v * 3 + d], acc[10]);
    }
    __shared__ float red[128][11];
#pragma unroll
    for (int i = 0; i < 11; i++) red[tid][i] = acc[i];
    __syncthreads();
    for (int off = 64; off > 0; off >>= 1) {
        if (tid < off) {
#pragma unroll
            for (int i = 0; i < 11; i++) red[tid][i] += red[tid + off][i];
        }
        __syncthreads();
    }
    if (tid == 0) {
#pragma unroll
        for (int s = 0; s < 10; s++) g_JS[jd * 10 + s] = red[0][s];
        g_JT[jd] = red[0][10];
    }
}

// ---------------- kernel 1: per-batch pose/rot/SE3 chain ----------------
__global__ void k_batch(const float* __restrict__ root_rotation,
                        const float* __restrict__ pose,
                        const float* __restrict__ shape,
                        const float* __restrict__ trans,
                        const float* __restrict__ hc,
                        const float* __restrict__ hm,
                        float* __restrict__ jout) {  // points at d_out + VOUT_ELEMS
    int b = blockIdx.x * blockDim.x + threadIdx.x;
    if (b >= BS) return;

    float pz[45];
#pragma unroll
    for (int c = 0; c < 45; c++) pz[c] = pose[b * 45 + c];

    float rot[15][9];
    for (int jj = 0; jj < 15; jj++) {
        float ax = hm[3 * jj], ay = hm[3 * jj + 1], az = hm[3 * jj + 2];
        for (int c = 0; c < 45; c++) {
            float p = pz[c];
            const float* h = hc + c * 45 + 3 * jj;
            ax = fmaf(p, h[0], ax);
            ay = fmaf(p, h[1], ay);
            az = fmaf(p, h[2], az);
        }
        float a2  = ax * ax + ay * ay + az * az + 1e-12f;
        float ang = sqrtf(a2);
        float inv = 1.0f / ang;
        float ux = ax * inv, uy = ay * inv, uz = az * inv;
        float cc = cosf(ang), ss = sinf(ang), oc = 1.0f - cc;
        float R00 = cc + oc * ux * ux;
        float R01 = -ss * uz + oc * ux * uy;
        float R02 =  ss * uy + oc * ux * uz;
        float R10 =  ss * uz + oc * ux * uy;
        float R11 = cc + oc * uy * uy;
        float R12 = -ss * ux + oc * uy * uz;
        float R20 = -ss * uy + oc * ux * uz;
        float R21 =  ss * ux + oc * uy * uz;
        float R22 = cc + oc * uz * uz;
        rot[jj][0]=R00; rot[jj][1]=R01; rot[jj][2]=R02;
        rot[jj][3]=R10; rot[jj][4]=R11; rot[jj][5]=R12;
        rot[jj][6]=R20; rot[jj][7]=R21; rot[jj][8]=R22;
        // pose_feat = (R - I), stored transposed [k][b]
        g_featT[(9*jj+0)*BS + b] = R00 - 1.0f;
        g_featT[(9*jj+1)*BS + b] = R01;
        g_featT[(9*jj+2)*BS + b] = R02;
        g_featT[(9*jj+3)*BS + b] = R10;
        g_featT[(9*jj+4)*BS + b] = R11 - 1.0f;
        g_featT[(9*jj+5)*BS + b] = R12;
        g_featT[(9*jj+6)*BS + b] = R20;
        g_featT[(9*jj+7)*BS + b] = R21;
        g_featT[(9*jj+8)*BS + b] = R22 - 1.0f;
    }

    float sh[10];
#pragma unroll
    for (int s = 0; s < 10; s++) {
        sh[s] = shape[b * 10 + s];
        g_featT[(135 + s) * BS + b] = sh[s];
    }
#pragma unroll
    for (int z = 0; z < 3; z++) g_featT[(145 + z) * BS + b] = 0.0f;

    // j_tpose
    float jt[16][3];
    for (int j = 0; j < 16; j++) {
#pragma unroll
        for (int d = 0; d < 3; d++) {
            float a = g_JT[j * 3 + d];
            const float* js = g_JS + (j * 3 + d) * 10;
#pragma unroll
            for (int s = 0; s < 10; s++) a = fmaf(js[s], sh[s], a);
            jt[j][d] = a;
        }
    }

    // SE3 chain (rows 3x4)
    float A[16][12];
    {
        float Rr[9];
#pragma unroll
        for (int i = 0; i < 9; i++) Rr[i] = root_rotation[b * 9 + i];
        float jx = jt[0][0], jy = jt[0][1], jz = jt[0][2];
#pragma unroll
        for (int r = 0; r < 3; r++) {
            A[0][r*4+0] = Rr[r*3+0];
            A[0][r*4+1] = Rr[r*3+1];
            A[0][r*4+2] = Rr[r*3+2];
        }
        A[0][3]  = jx - (Rr[0]*jx + Rr[1]*jy + Rr[2]*jz);
        A[0][7]  = jy - (Rr[3]*jx + Rr[4]*jy + Rr[5]*jz);
        A[0][11] = jz - (Rr[6]*jx + Rr[7]*jy + Rr[8]*jz);
    }
    for (int i = 1; i < 16; i++) {
        int p = c_parent[i];
        const float* Ri = rot[i - 1];
        float jx = jt[i][0], jy = jt[i][1], jz = jt[i][2];
        float t0 = jx - (Ri[0]*jx + Ri[1]*jy + Ri[2]*jz);
        float t1 = jy - (Ri[3]*jx + Ri[4]*jy + Ri[5]*jz);
        float t2 = jz - (Ri[6]*jx + Ri[7]*jy + Ri[8]*jz);
        const float* P = A[p];
        float* O = A[i];
#pragma unroll
        for (int r = 0; r < 3; r++) {
            float p0 = P[r*4+0], p1 = P[r*4+1], p2 = P[r*4+2];
            O[r*4+0] = p0*Ri[0] + p1*Ri[3] + p2*Ri[6];
            O[r*4+1] = p0*Ri[1] + p1*Ri[4] + p2*Ri[7];
            O[r*4+2] = p0*Ri[2] + p1*Ri[5] + p2*Ri[8];
            O[r*4+3] = p0*t0 + p1*t1 + p2*t2 + P[r*4+3];
        }
    }
    // store SE3 TRANSPOSED: [e][b] so k_main reads are coalesced
    for (int j = 0; j < 16; j++)
#pragma unroll
        for (int e = 0; e < 12; e++) g_se3T[(j * 12 + e) * BS + b] = A[j][e];

    // center / offset
    float cx = jt[0][0], cy = jt[0][1], cz = jt[0][2];
    float ox = trans[b*3+0] - cx, oy = trans[b*3+1] - cy, oz = trans[b*3+2] - cz;
    g_off[0*BS + b] = ox;
    g_off[1*BS + b] = oy;
    g_off[2*BS + b] = oz;

    // joint outputs (non-tip entries of j_out)
    float jl[16][3];
    jl[0][0] = cx; jl[0][1] = cy; jl[0][2] = cz;
    for (int i = 1; i < 16; i++) {
        int p = c_parent[i];
        const float* P = A[p];
        float jx = jt[i][0], jy = jt[i][1], jz = jt[i][2];
        jl[i][0] = P[0]*jx + P[1]*jy + P[2]*jz  + P[3];
        jl[i][1] = P[4]*jx + P[5]*jy + P[6]*jz  + P[7];
        jl[i][2] = P[8]*jx + P[9]*jy + P[10]*jz + P[11];
    }
    for (int pos = 0; pos < 21; pos++) {
        int src = c_neworder[pos];
        if (src < 16) {
            float* jo = jout + ((size_t)b * 21 + pos) * 3;
            jo[0] = jl[src][0] + ox;
            jo[1] = jl[src][1] + oy;
            jo[2] = jl[src][2] + oz;
        }
    }
}

// ---------------- kernel 2: main fused GEMM + LBS, 2 vertices/warp ----------------
union F4 { float4 v; float a[4]; };

__global__ void __launch_bounds__(256, 2) k_main(const float* __restrict__ v_template,
                                                 const float* __restrict__ weights,
                                                 float* __restrict__ out) {
    __shared__ float s_out[16 * RS];   // [v_local][b_local*3+d] (padded rows)

    int warp = threadIdx.x >> 5;
    int lane = threadIdx.x & 31;
    int v0 = blockIdx.x * 16 + warp * 2;
    int v1 = v0 + 1;
    bool valid0 = (v0 < NV);
    bool valid1 = (v1 < NV);
    int v0c = valid0 ? v0 : (NV - 1);   // clamped for safe loads
    int v1c = valid1 ? v1 : (NV - 1);
    int b0 = blockIdx.y * 128 + lane * 4;

    if (valid0 || valid1) {
        const float* dA0 = g_dirs + (v0c * 3 + 0) * KP;
        const float* dA1 = g_dirs + (v0c * 3 + 1) * KP;
        const float* dA2 = g_dirs + (v0c * 3 + 2) * KP;
        const float* dB0 = g_dirs + (v1c * 3 + 0) * KP;
        const float* dB1 = g_dirs + (v1c * 3 + 1) * KP;
        const float* dB2 = g_dirs + (v1c * 3 + 2) * KP;

        float ax[4]={0,0,0,0}, ay[4]={0,0,0,0}, az[4]={0,0,0,0};
        float bx[4]={0,0,0,0}, by[4]={0,0,0,0}, bz[4]={0,0,0,0};

        for (int k0 = 0; k0 < KP; k0 += 4) {
            F4 pa0, pa1, pa2, pb0, pb1, pb2;
            pa0.v = *reinterpret_cast<const float4*>(dA0 + k0);
            pa1.v = *reinterpret_cast<const float4*>(dA1 + k0);
            pa2.v = *reinterpret_cast<const float4*>(dA2 + k0);
            pb0.v = *reinterpret_cast<const float4*>(dB0 + k0);
            pb1.v = *reinterpret_cast<const float4*>(dB1 + k0);
            pb2.v = *reinterpret_cast<const float4*>(dB2 + k0);
#pragma unroll
            for (int kk = 0; kk < 4; kk++) {
                F4 f;
                f.v = *reinterpret_cast<const float4*>(g_featT + (k0 + kk) * BS + b0);
#pragma unroll
                for (int i = 0; i < 4; i++) {
                    ax[i] = fmaf(pa0.a[kk], f.a[i], ax[i]);
                    ay[i] = fmaf(pa1.a[kk], f.a[i], ay[i]);
                    az[i] = fmaf(pa2.a[kk], f.a[i], az[i]);
                    bx[i] = fmaf(pb0.a[kk], f.a[i], bx[i]);
                    by[i] = fmaf(pb1.a[kk], f.a[i], by[i]);
                    bz[i] = fmaf(pb2.a[kk], f.a[i], bz[i]);
                }
            }
        }

        // add v_template -> rest-pose positions (reuse acc arrays as h)
        {
            float t0 = v_template[v0c * 3 + 0];
            float t1 = v_template[v0c * 3 + 1];
            float t2 = v_template[v0c * 3 + 2];
            float u0 = v_template[v1c * 3 + 0];
            float u1 = v_template[v1c * 3 + 1];
            float u2 = v_template[v1c * 3 + 2];
#pragma unroll
            for (int i = 0; i < 4; i++) {
                ax[i] += t0; ay[i] += t1; az[i] += t2;
                bx[i] += u0; by[i] += u1; bz[i] += u2;
            }
        }

        float rA0[4]={0,0,0,0}, rA1[4]={0,0,0,0}, rA2[4]={0,0,0,0};
        float rB0[4]={0,0,0,0}, rB1[4]={0,0,0,0}, rB2[4]={0,0,0,0};

#pragma unroll
        for (int j = 0; j < 16; j++) {
            float wA = weights[v0c * 16 + j];
            float wB = weights[v1c * 16 + j];
            const float* base = g_se3T + (j * 12) * BS + b0;
#pragma unroll
            for (int r = 0; r < 3; r++) {
                F4 m0, m1, m2, m3;
                m0.v = *reinterpret_cast<const float4*>(base + (r*4+0) * BS);
                m1.v = *reinterpret_cast<const float4*>(base + (r*4+1) * BS);
                m2.v = *reinterpret_cast<const float4*>(base + (r*4+2) * BS);
                m3.v = *reinterpret_cast<const float4*>(base + (r*4+3) * BS);
                float* rA = (r == 0) ? rA0 : (r == 1) ? rA1 : rA2;
                float* rB = (r == 0) ? rB0 : (r == 1) ? rB1 : rB2;
#pragma unroll
                for (int i = 0; i < 4; i++) {
                    float tA = fmaf(m0.a[i], ax[i], fmaf(m1.a[i], ay[i], fmaf(m2.a[i], az[i], m3.a[i])));
                    rA[i] = fmaf(wA, tA, rA[i]);
                    float tB = fmaf(m0.a[i], bx[i], fmaf(m1.a[i], by[i], fmaf(m2.a[i], bz[i], m3.a[i])));
                    rB[i] = fmaf(wB, tB, rB[i]);
                }
            }
        }

        F4 off0, off1, off2;
        off0.v = *reinterpret_cast<const float4*>(g_off + 0 * BS + b0);
        off1.v = *reinterpret_cast<const float4*>(g_off + 1 * BS + b0);
        off2.v = *reinterpret_cast<const float4*>(g_off + 2 * BS + b0);

        int vl0 = warp * 2;
        int vl1 = vl0 + 1;
#pragma unroll
        for (int i = 0; i < 4; i++) {
            int bl = lane * 4 + i;
            float oA0 = rA0[i] + off0.a[i];
            float oA1 = rA1[i] + off1.a[i];
            float oA2 = rA2[i] + off2.a[i];
            float oB0 = rB0[i] + off0.a[i];
            float oB1 = rB1[i] + off1.a[i];
            float oB2 = rB2[i] + off2.a[i];
            if (valid0) {
                s_out[vl0 * RS + bl * 3 + 0] = oA0;
                s_out[vl0 * RS + bl * 3 + 1] = oA1;
                s_out[vl0 * RS + bl * 3 + 2] = oA2;
            }
            if (valid1) {
                s_out[vl1 * RS + bl * 3 + 0] = oB0;
                s_out[vl1 * RS + bl * 3 + 1] = oB1;
                s_out[vl1 * RS + bl * 3 + 2] = oB2;
            }
            // tip scatter
            int posA = -1, posB = -1;
            if      (v0 == 745) posA = 4;
            else if (v0 == 333) posA = 8;
            else if (v0 == 444) posA = 12;
            else if (v0 == 555) posA = 16;
            else if (v0 == 672) posA = 20;
            if      (v1 == 745) posB = 4;
            else if (v1 == 333) posB = 8;
            else if (v1 == 444) posB = 12;
            else if (v1 == 555) posB = 16;
            else if (v1 == 672) posB = 20;
            if (posA >= 0) {
                int b = b0 + i;
                float* jo = out + (size_t)VOUT_ELEMS + ((size_t)b * 21 + posA) * 3;
                jo[0] = oA0; jo[1] = oA1; jo[2] = oA2;
            }
            if (posB >= 0) {
                int b = b0 + i;
                float* jo = out + (size_t)VOUT_ELEMS + ((size_t)b * 21 + posB) * 3;
                jo[0] = oB0; jo[1] = oB1; jo[2] = oB2;
            }
        }
    }

    __syncthreads();

    // cooperative coalesced readout: per batch, the block's 16 vertices are
    // 48 contiguous floats in out[(b*NV + v_base)*3 ...]
    int v_base = blockIdx.x * 16;
    int b_base = blockIdx.y * 128;
    int nv_here = NV - v_base;
    if (nv_here > 16) nv_here = 16;
    int row_floats = nv_here * 3;
#pragma unroll 4
    for (int t = threadIdx.x; t < 128 * 48; t += 256) {
        int b_local = t / 48;
        int e = t % 48;
        if (e < row_floats) {
            int v_local = e / 3;
            int d = e - v_local * 3;
            out[((size_t)(b_base + b_local) * NV + v_base) * 3 + e] =
                s_out[v_local * RS + b_local * 3 + d];
        }
    }
}

// ---------------- launch ----------------
extern "C" void kernel_launch(void* const* d_in, const int* in_sizes, int n_in,
                              void* d_out, int out_size) {
    const float* root_rotation = (const float*)d_in[0];
    const float* pose          = (const float*)d_in[1];
    const float* shape         = (const float*)d_in[2];
    const float* trans         = (const float*)d_in[3];
    const float* hc            = (const float*)d_in[4];
    const float* hm            = (const float*)d_in[5];
    const float* shapedirs     = (const float*)d_in[6];
    const float* posedirs      = (const float*)d_in[7];
    const float* v_template    = (const float*)d_in[8];
    const float* Jreg          = (const float*)d_in[9];
    const float* weights       = (const float*)d_in[10];
    float* out = (float*)d_out;

    int dirs_total = NV * 3 * KP;
    k_build_dirs<<<(dirs_total + 255) / 256, 256>>>(posedirs, shapedirs);
    k_jreg<<<48, 128>>>(Jreg, shapedirs, v_template);
    k_batch<<<BS / 128, 128>>>(root_rotation, pose, shape, trans, hc, hm,
                               out + VOUT_ELEMS);
    dim3 grid((NV + 15) / 16, BS / 128);
    k_main<<<grid, 256>>>(v_template, weights, out);
}